// round 7
// baseline (speedup 1.0000x reference)
#include <cuda_runtime.h>
#include <cuda_fp16.h>
#include <math.h>
#include <stdint.h>

// ---------------- Problem constants ----------------
#define B_   4
#define S_   4096
#define DM_  128
#define DD_  64
#define NCH_ 64              // key chunks per batch (S/64)
#define SPLIT_ 4
#define NCHS_ (NCH_/SPLIT_)  // 16 chunks per split CTA
#define NROW_ (B_*S_)        // 16384

// fold softmax scale and log2(e) into Q: exp(s/8) = exp2(s*0.125*log2e)
#define QSCALE_ 0.18033688011112042f

// ---------------- attn smem layout (bytes) ----------------
#define KROW_B 400
#define KBUF_B (64 * KROW_B)          // 25600
#define VROW_B 144
#define VBUF_B (64 * VROW_B)          // 9216
#define SM_K0 0
#define SM_K1 KBUF_B
#define SM_V0 (2 * KBUF_B)
#define SM_V1 (2 * KBUF_B + VBUF_B)
#define SMEM_TOTAL_ (2 * KBUF_B + 2 * VBUF_B)  // 69632

// ---------------- proj smem layout ----------------
#define SM_WP   0                       // 2 halves x [64 rows x 400B] = 51200
#define SM_XS   51200                   // X tile [64 rows x 132 words(528B)] = 33792
#define PROJ_SMEM_ (SM_XS + 64*528)     // 84992

// Scratch (alloc-guard-safe device globals)
__device__ float  g_Q [(size_t)NROW_ * DD_];           // scaled fp32
__device__ float  g_Kp[(size_t)NROW_ * DD_];           // tf32 bits, permuted
__device__ __half g_Vh[(size_t)NROW_ * DD_];           // fp16 row-major
__device__ float  g_Op[(size_t)SPLIT_ * NROW_ * DD_];  // partial O (unnormalized)
__device__ float  g_l [(size_t)SPLIT_ * NROW_];        // partial row sums

// ---------------- helpers ----------------
__device__ __forceinline__ uint32_t smem_u32(const void* p) {
    uint32_t a;
    asm("{ .reg .u64 t; cvta.to.shared.u64 t, %1; cvt.u32.u64 %0, t; }" : "=r"(a) : "l"(p));
    return a;
}
__device__ __forceinline__ uint32_t f2tf32(float f) {
    uint32_t r; asm("cvt.rna.tf32.f32 %0, %1;" : "=r"(r) : "f"(f)); return r;
}
__device__ __forceinline__ float ex2f(float f) {
    float r; asm("ex2.approx.f32 %0, %1;" : "=f"(r) : "f"(f)); return r;
}
__device__ __forceinline__ uint32_t f16x2(float hi, float lo) {
    __half2 h = __floats2half2_rn(lo, hi);
    return *(uint32_t*)&h;
}
__device__ __forceinline__ void cpasync16(uint32_t dst, const void* src) {
    asm volatile("cp.async.cg.shared.global [%0], [%1], 16;" :: "r"(dst), "l"(src) : "memory");
}
#define CP_COMMIT asm volatile("cp.async.commit_group;" ::: "memory")
#define CP_WAIT0  asm volatile("cp.async.wait_group 0;" ::: "memory")

__device__ __forceinline__ void mma_tf32(float c[4], const uint32_t a[4],
                                         uint32_t b0, uint32_t b1) {
    asm("mma.sync.aligned.m16n8k8.row.col.f32.tf32.tf32.f32 "
        "{%0,%1,%2,%3}, {%4,%5,%6,%7}, {%8,%9}, {%0,%1,%2,%3};"
        : "+f"(c[0]), "+f"(c[1]), "+f"(c[2]), "+f"(c[3])
        : "r"(a[0]), "r"(a[1]), "r"(a[2]), "r"(a[3]), "r"(b0), "r"(b1));
}
__device__ __forceinline__ void mma_fp16(float c[4], const uint32_t a[4],
                                         uint32_t b0, uint32_t b1) {
    asm("mma.sync.aligned.m16n8k16.row.col.f32.f16.f16.f32 "
        "{%0,%1,%2,%3}, {%4,%5,%6,%7}, {%8,%9}, {%0,%1,%2,%3};"
        : "+f"(c[0]), "+f"(c[1]), "+f"(c[2]), "+f"(c[3])
        : "r"(a[0]), "r"(a[1]), "r"(a[2]), "r"(a[3]), "r"(b0), "r"(b1));
}

// ---------------------------------------------------------------------------
// Tensor-core projection (tf32 mma). CTA = 64 rows, 128 threads, 4 warps.
// Reuses the attention QK fragment pattern: W permuted into the same smem
// layout as g_Kp chunks (2 halves for K=128), X staged row-major (528B rows).
// z=0: Q scaled fp32; z=1: K tf32, fragment-permuted; z=2: V fp16.
// ---------------------------------------------------------------------------
__global__ __launch_bounds__(128) void proj_tc(
    const float* __restrict__ Xq, const float* __restrict__ Xk, const float* __restrict__ Xv,
    const float* __restrict__ Wq, const float* __restrict__ bq,
    const float* __restrict__ Wk, const float* __restrict__ bk,
    const float* __restrict__ Wv, const float* __restrict__ bv)
{
    const float *X, *W, *bias;
    const int z = blockIdx.z;
    if (z == 0)      { X = Xq; W = Wq; bias = bq; }
    else if (z == 1) { X = Xk; W = Wk; bias = bk; }
    else             { X = Xv; W = Wv; bias = bv; }

    extern __shared__ __align__(16) char sm[];
    char* smc = sm;
    float* Xs = (float*)(sm + SM_XS);
    const uint32_t smb = smem_u32(sm);
    const int tid = threadIdx.x;
    const int w = tid >> 5, lane = tid & 31;
    const int g = lane >> 2, tg = lane & 3;
    const int row0 = blockIdx.x * 64;

    // stage X tile [64 x 128] fp32, row stride 528B (132 words; 132%32=4 -> LDS conflict-free)
    #pragma unroll
    for (int t = 0; t < 16; t++) {
        int idx = tid + t * 128;
        int r = idx >> 5, c16 = idx & 31;
        cpasync16(smb + SM_XS + r * 528 + c16 * 16,
                  X + (size_t)(row0 + r) * DM_ + c16 * 4);
    }
    CP_COMMIT;
    // W permuted into 2 half-buffers of the g_Kp layout:
    // perm index p at row n: element W[4*(p%16) + p/16 + 64*h][n], tf32-rounded
    #pragma unroll
    for (int t = 0; t < 64; t++) {
        int idx = tid + t * 128;
        int h = idx >> 12, rem = idx & 4095;
        int n = rem >> 6, p = rem & 63;
        float wv = W[(size_t)(4 * (p & 15) + (p >> 4) + 64 * h) * DD_ + n];
        *(uint32_t*)(smc + SM_WP + h * KBUF_B + n * KROW_B + (p >> 4) * 96 + (p & 15) * 4)
            = f2tf32(wv);
    }
    CP_WAIT0;
    __syncthreads();

    float c[8][4];
    #pragma unroll
    for (int j = 0; j < 8; j++) { c[j][0]=0.f; c[j][1]=0.f; c[j][2]=0.f; c[j][3]=0.f; }

    const int r1 = w * 16 + g;
    #pragma unroll
    for (int h = 0; h < 2; h++) {
        // A fragments from Xs (conflict-free scalar LDS)
        uint32_t aa[8][4];
        #pragma unroll
        for (int s = 0; s < 8; s++) {
            int cb = 64 * h + 8 * s + tg;
            aa[s][0] = f2tf32(Xs[ r1      * 132 + cb]);
            aa[s][1] = f2tf32(Xs[(r1 + 8) * 132 + cb]);
            aa[s][2] = f2tf32(Xs[ r1      * 132 + cb + 4]);
            aa[s][3] = f2tf32(Xs[(r1 + 8) * 132 + cb + 4]);
        }
        const char* kbase = smc + SM_WP + h * KBUF_B + g * KROW_B + tg * 96;
        #pragma unroll
        for (int j = 0; j < 8; j++) {
            const char* p = kbase + j * (8 * KROW_B);
            float4 f0 = *(const float4*)(p);
            float4 f1 = *(const float4*)(p + 16);
            float4 f2 = *(const float4*)(p + 32);
            float4 f3 = *(const float4*)(p + 48);
            uint32_t kb[16] = {
                __float_as_uint(f0.x), __float_as_uint(f0.y), __float_as_uint(f0.z), __float_as_uint(f0.w),
                __float_as_uint(f1.x), __float_as_uint(f1.y), __float_as_uint(f1.z), __float_as_uint(f1.w),
                __float_as_uint(f2.x), __float_as_uint(f2.y), __float_as_uint(f2.z), __float_as_uint(f2.w),
                __float_as_uint(f3.x), __float_as_uint(f3.y), __float_as_uint(f3.z), __float_as_uint(f3.w) };
            #pragma unroll
            for (int s = 0; s < 8; s++)
                mma_tf32(c[j], aa[s], kb[2*s], kb[2*s+1]);
        }
    }

    // epilogue: bias + store per z
    const size_t rg1 = (size_t)(row0 + r1);
    const size_t rg2 = rg1 + 8;
    #pragma unroll
    for (int j = 0; j < 8; j++) {
        int n0 = j * 8 + 2 * tg;
        float b0 = bias[n0], b1 = bias[n0 + 1];
        float v00 = c[j][0] + b0, v01 = c[j][1] + b1;   // row r1
        float v10 = c[j][2] + b0, v11 = c[j][3] + b1;   // row r1+8
        if (z == 0) {
            *(float2*)(g_Q + rg1 * DD_ + n0) = make_float2(v00 * QSCALE_, v01 * QSCALE_);
            *(float2*)(g_Q + rg2 * DD_ + n0) = make_float2(v10 * QSCALE_, v11 * QSCALE_);
        } else if (z == 1) {
            int p0 = (n0 & 3) * 16 + (n0 >> 2);
            int p1 = ((n0 + 1) & 3) * 16 + ((n0 + 1) >> 2);
            g_Kp[rg1 * DD_ + p0] = __uint_as_float(f2tf32(v00));
            g_Kp[rg1 * DD_ + p1] = __uint_as_float(f2tf32(v01));
            g_Kp[rg2 * DD_ + p0] = __uint_as_float(f2tf32(v10));
            g_Kp[rg2 * DD_ + p1] = __uint_as_float(f2tf32(v11));
        } else {
            *(uint32_t*)((char*)g_Vh + (rg1 * DD_ + n0) * 2) = f16x2(v01, v00);
            *(uint32_t*)((char*)g_Vh + (rg2 * DD_ + n0) * 2) = f16x2(v11, v10);
        }
    }
}

// ---------------------------------------------------------------------------
// Flash attention, split-K(4). CTA = 64 q-rows x 16 key-chunks, 128 threads.
// Writes unnormalized partial O + partial l; no max-tracking.
// ---------------------------------------------------------------------------
__global__ __launch_bounds__(128, 3) void attn_mma(void)
{
    extern __shared__ __align__(16) char sm[];
    char* smc = sm;
    const uint32_t smb = smem_u32(sm);
    const int tid  = threadIdx.x;
    const int w    = tid >> 5, lane = tid & 31;
    const int g    = lane >> 2, tg = lane & 3;
    const int b    = blockIdx.y;
    const int q0   = blockIdx.x * 64;
    const int sp   = blockIdx.z;
    const int ch0  = sp * NCHS_;

    // ---- Q fragments (registers, all chunks) ----
    uint32_t qf[8][4];
    {
        const float* qg  = g_Q + ((size_t)b * S_ + q0 + w * 16 + g) * DD_;
        const float* qg8 = qg + 8 * DD_;
        #pragma unroll
        for (int s = 0; s < 8; s++) {
            qf[s][0] = f2tf32(qg [8*s + tg]);
            qf[s][1] = f2tf32(qg8[8*s + tg]);
            qf[s][2] = f2tf32(qg [8*s + tg + 4]);
            qf[s][3] = f2tf32(qg8[8*s + tg + 4]);
        }
    }

    const float*  KpB = g_Kp + (size_t)b * S_ * DD_;
    const __half* VhB = g_Vh + (size_t)b * S_ * DD_;

    const uint32_t vlaneoff =
        (uint32_t)((((lane >> 3) & 1) * 8 + (lane & 7)) * VROW_B + ((lane >> 4) * 8) * 2);

    float o[8][4];
    #pragma unroll
    for (int j = 0; j < 8; j++) { o[j][0]=0.f; o[j][1]=0.f; o[j][2]=0.f; o[j][3]=0.f; }
    float lg = 0.f, lg8 = 0.f;

    auto load_chunk = [&](int ci, int buf) {
        const float* kc = KpB + (size_t)ci * (64 * DD_);
        const uint32_t kdst0 = smb + (buf ? SM_K1 : SM_K0);
        #pragma unroll
        for (int t = 0; t < 8; t++) {
            int idx = tid + t * 128;
            int r = idx >> 4, tgb = (idx >> 2) & 3, v16 = idx & 3;
            cpasync16(kdst0 + r * KROW_B + tgb * 96 + v16 * 16,
                      kc + r * 64 + tgb * 16 + v16 * 4);
        }
        const __half* vc = VhB + (size_t)ci * (64 * DD_);
        const uint32_t vdst0 = smb + (buf ? SM_V1 : SM_V0);
        #pragma unroll
        for (int t = 0; t < 4; t++) {
            int idx = tid + t * 128;
            int r = idx >> 3, c16 = idx & 7;
            cpasync16(vdst0 + r * VROW_B + c16 * 16, vc + r * DD_ + c16 * 8);
        }
    };

    load_chunk(ch0, 0); CP_COMMIT;
    CP_WAIT0; __syncthreads();

    #pragma unroll 1
    for (int i = 0; i < NCHS_; i++) {
        const int buf = i & 1;
        if (i + 1 < NCHS_) { load_chunk(ch0 + i + 1, buf ^ 1); CP_COMMIT; }

        // ---- S = Q K^T ----
        float c[8][4];
        #pragma unroll
        for (int j = 0; j < 8; j++) { c[j][0]=0.f; c[j][1]=0.f; c[j][2]=0.f; c[j][3]=0.f; }

        const char* kbase = smc + (buf ? SM_K1 : SM_K0) + g * KROW_B + tg * 96;
        #pragma unroll
        for (int j = 0; j < 8; j++) {
            const char* p = kbase + j * (8 * KROW_B);
            float4 f0 = *(const float4*)(p);
            float4 f1 = *(const float4*)(p + 16);
            float4 f2 = *(const float4*)(p + 32);
            float4 f3 = *(const float4*)(p + 48);
            uint32_t kb[16] = {
                __float_as_uint(f0.x), __float_as_uint(f0.y), __float_as_uint(f0.z), __float_as_uint(f0.w),
                __float_as_uint(f1.x), __float_as_uint(f1.y), __float_as_uint(f1.z), __float_as_uint(f1.w),
                __float_as_uint(f2.x), __float_as_uint(f2.y), __float_as_uint(f2.z), __float_as_uint(f2.w),
                __float_as_uint(f3.x), __float_as_uint(f3.y), __float_as_uint(f3.z), __float_as_uint(f3.w) };
            #pragma unroll
            for (int s = 0; s < 8; s++)
                mma_tf32(c[j], qf[s], kb[2*s], kb[2*s+1]);
        }

        // ---- P = exp2(S), partial row sums ----
        #pragma unroll
        for (int j = 0; j < 8; j++) {
            c[j][0] = ex2f(c[j][0]); c[j][1] = ex2f(c[j][1]);
            c[j][2] = ex2f(c[j][2]); c[j][3] = ex2f(c[j][3]);
            lg  += c[j][0] + c[j][1];
            lg8 += c[j][2] + c[j][3];
        }

        // ---- O += P V ----
        const uint32_t vb0 = smb + (buf ? SM_V1 : SM_V0) + vlaneoff;
        #pragma unroll
        for (int s = 0; s < 4; s++) {
            uint32_t pa[4];
            pa[0] = f16x2(c[2*s  ][1], c[2*s  ][0]);
            pa[1] = f16x2(c[2*s  ][3], c[2*s  ][2]);
            pa[2] = f16x2(c[2*s+1][1], c[2*s+1][0]);
            pa[3] = f16x2(c[2*s+1][3], c[2*s+1][2]);
            #pragma unroll
            for (int jp = 0; jp < 4; jp++) {
                uint32_t addr = vb0 + s * (16 * VROW_B) + jp * 32;
                uint32_t v0, v1, v2, v3;
                asm volatile("ldmatrix.sync.aligned.m8n8.x4.trans.shared.b16 "
                             "{%0,%1,%2,%3}, [%4];"
                             : "=r"(v0), "=r"(v1), "=r"(v2), "=r"(v3) : "r"(addr));
                mma_fp16(o[2*jp],     pa, v0, v1);
                mma_fp16(o[2*jp + 1], pa, v2, v3);
            }
        }

        CP_WAIT0;
        __syncthreads();
    }

    // ---- epilogue: partial l (quad-reduced) + unnormalized partial O ----
    lg  += __shfl_xor_sync(0xffffffffu, lg , 1);
    lg  += __shfl_xor_sync(0xffffffffu, lg , 2);
    lg8 += __shfl_xor_sync(0xffffffffu, lg8, 1);
    lg8 += __shfl_xor_sync(0xffffffffu, lg8, 2);

    const size_t rowg = (size_t)b * S_ + q0 + w * 16 + g;
    float* op = g_Op + ((size_t)sp * NROW_ + rowg) * DD_;
    #pragma unroll
    for (int j = 0; j < 8; j++) {
        *(float2*)(op + j * 8 + tg * 2)           = make_float2(o[j][0], o[j][1]);
        *(float2*)(op + 8 * DD_ + j * 8 + tg * 2) = make_float2(o[j][2], o[j][3]);
    }
    if (tg == 0) {
        g_l[(size_t)sp * NROW_ + rowg]     = lg;
        g_l[(size_t)sp * NROW_ + rowg + 8] = lg8;
    }
}

// ---------------------------------------------------------------------------
// Split-K reduce: out[row] = sum_s Op[s][row] / sum_s l[s][row]
// ---------------------------------------------------------------------------
__global__ __launch_bounds__(256) void reduce_k(float* __restrict__ Out)
{
    const int idx = blockIdx.x * 256 + threadIdx.x;
    const int rid = idx >> 4;          // row 0..16383
    const int dg  = idx & 15;          // float4 group
    float4 a = make_float4(0.f, 0.f, 0.f, 0.f);
    float ls = 0.f;
    #pragma unroll
    for (int s = 0; s < SPLIT_; s++) {
        float4 v = *(const float4*)(g_Op + ((size_t)s * NROW_ + rid) * DD_ + dg * 4);
        a.x += v.x; a.y += v.y; a.z += v.z; a.w += v.w;
        ls += g_l[(size_t)s * NROW_ + rid];
    }
    const float inv = 1.0f / ls;
    *(float4*)(Out + (size_t)rid * DD_ + dg * 4) =
        make_float4(a.x * inv, a.y * inv, a.z * inv, a.w * inv);
}

// ---------------------------------------------------------------------------
// kernel_launch — graph-capturable, allocation-free
// Inputs (metadata order): q_in, k_in, v_in, Wq, bq, Wk, bk, Wv, bv
// ---------------------------------------------------------------------------
extern "C" void kernel_launch(void* const* d_in, const int* in_sizes, int n_in,
                              void* d_out, int out_size)
{
    const float* q_in = (const float*)d_in[0];
    const float* k_in = (const float*)d_in[1];
    const float* v_in = (const float*)d_in[2];
    const float* Wq   = (const float*)d_in[3];
    const float* bq   = (const float*)d_in[4];
    const float* Wk   = (const float*)d_in[5];
    const float* bk   = (const float*)d_in[6];
    const float* Wv   = (const float*)d_in[7];
    const float* bv   = (const float*)d_in[8];
    float* out = (float*)d_out;

    cudaFuncSetAttribute(proj_tc, cudaFuncAttributeMaxDynamicSharedMemorySize,
                         PROJ_SMEM_);
    cudaFuncSetAttribute(attn_mma, cudaFuncAttributeMaxDynamicSharedMemorySize,
                         SMEM_TOTAL_);

    proj_tc<<<dim3(NROW_ / 64, 1, 3), 128, PROJ_SMEM_>>>(
        q_in, k_in, v_in, Wq, bq, Wk, bk, Wv, bv);

    attn_mma<<<dim3(S_ / 64, B_, SPLIT_), 128, SMEM_TOTAL_>>>();

    reduce_k<<<(NROW_ * 16) / 256, 256>>>(out);
}

// round 9
// speedup vs baseline: 1.8918x; 1.8918x over previous
#include <cuda_runtime.h>
#include <cuda_fp16.h>
#include <math.h>
#include <stdint.h>

// ---------------- Problem constants ----------------
#define B_   4
#define S_   4096
#define DM_  128
#define DD_  64
#define NCH_ 64
#define SPLIT_ 4
#define NCHS_ (NCH_/SPLIT_)  // 16
#define NROW_ (B_*S_)        // 16384

// fold softmax scale and log2(e) into Q: exp(s/8) = exp2(s*0.125*log2e)
#define QSCALE_ 0.18033688011112042f

// ---------------- attn smem (bytes): K/V fp16, 64 rows x 144B ----------------
#define TROW_B 144
#define TBUF_B (64 * TROW_B)          // 9216
#define SM_K0 0
#define SM_K1 TBUF_B
#define SM_V0 (2 * TBUF_B)
#define SM_V1 (3 * TBUF_B)
#define SMEM_ATTN_ (4 * TBUF_B)       // 36864

// ---------------- proj smem ----------------
#define SM_W  0                        // W fp16 staged: 128 rows x 144B = 18432
#define SM_X  18432                    // X fp32 staged: 64 rows x 528B  = 33792
#define PROJ_SMEM_ (SM_X + 64*528)     // 52224

// Scratch (alloc-guard-safe device globals) — all dense fp16 [row][64]
__device__ __half g_Qh[(size_t)NROW_ * DD_];
__device__ __half g_Kh[(size_t)NROW_ * DD_];
__device__ __half g_Vh[(size_t)NROW_ * DD_];
__device__ __half g_Wh[3 * DM_ * DD_];                 // pre-converted weights
__device__ float  g_Op[(size_t)SPLIT_ * NROW_ * DD_];  // partial O (unnormalized)
__device__ float  g_l [(size_t)SPLIT_ * NROW_];        // partial row sums

// ---------------- helpers ----------------
__device__ __forceinline__ uint32_t smem_u32(const void* p) {
    uint32_t a;
    asm("{ .reg .u64 t; cvta.to.shared.u64 t, %1; cvt.u32.u64 %0, t; }" : "=r"(a) : "l"(p));
    return a;
}
__device__ __forceinline__ float ex2f(float f) {
    float r; asm("ex2.approx.f32 %0, %1;" : "=f"(r) : "f"(f)); return r;
}
__device__ __forceinline__ uint32_t f16x2(float hi, float lo) {
    __half2 h = __floats2half2_rn(lo, hi);
    return *(uint32_t*)&h;
}
__device__ __forceinline__ void cpasync16(uint32_t dst, const void* src) {
    asm volatile("cp.async.cg.shared.global [%0], [%1], 16;" :: "r"(dst), "l"(src) : "memory");
}
#define CP_COMMIT asm volatile("cp.async.commit_group;" ::: "memory")
#define CP_WAIT0  asm volatile("cp.async.wait_group 0;" ::: "memory")

__device__ __forceinline__ void mma_fp16(float c[4], const uint32_t a[4],
                                         uint32_t b0, uint32_t b1) {
    asm("mma.sync.aligned.m16n8k16.row.col.f32.f16.f16.f32 "
        "{%0,%1,%2,%3}, {%4,%5,%6,%7}, {%8,%9}, {%0,%1,%2,%3};"
        : "+f"(c[0]), "+f"(c[1]), "+f"(c[2]), "+f"(c[3])
        : "r"(a[0]), "r"(a[1]), "r"(a[2]), "r"(a[3]), "r"(b0), "r"(b1));
}
__device__ __forceinline__ void ldsm4(uint32_t& r0, uint32_t& r1, uint32_t& r2,
                                      uint32_t& r3, uint32_t a) {
    asm volatile("ldmatrix.sync.aligned.m8n8.x4.shared.b16 {%0,%1,%2,%3}, [%4];"
                 : "=r"(r0), "=r"(r1), "=r"(r2), "=r"(r3) : "r"(a));
}
__device__ __forceinline__ void ldsm4t(uint32_t& r0, uint32_t& r1, uint32_t& r2,
                                       uint32_t& r3, uint32_t a) {
    asm volatile("ldmatrix.sync.aligned.m8n8.x4.trans.shared.b16 {%0,%1,%2,%3}, [%4];"
                 : "=r"(r0), "=r"(r1), "=r"(r2), "=r"(r3) : "r"(a));
}

// ---------------------------------------------------------------------------
// w_prep: convert the three 128x64 fp32 weight matrices to fp16 (coalesced)
// ---------------------------------------------------------------------------
__global__ __launch_bounds__(256) void w_prep(
    const float* __restrict__ Wq, const float* __restrict__ Wk,
    const float* __restrict__ Wv)
{
    const int z = blockIdx.x;
    const float* W = (z == 0) ? Wq : (z == 1) ? Wk : Wv;
    __half2* dst = (__half2*)(g_Wh + (size_t)z * DM_ * DD_);
    const float2* src = (const float2*)W;
    #pragma unroll
    for (int t = 0; t < 16; t++) {
        int e2 = threadIdx.x + t * 256;      // 4096 pairs
        float2 v = src[e2];
        dst[e2] = __floats2half2_rn(v.x, v.y);
    }
}

// ---------------------------------------------------------------------------
// Projection (fp16 mma): CTA = 64 rows, 128 threads. z selects Q/K/V.
// X staged fp32 (cp.async), A-frags converted in registers; W staged fp16,
// B-frags via ldmatrix.trans (same pattern as attention's V).
// ---------------------------------------------------------------------------
__global__ __launch_bounds__(128, 3) void proj_tc(
    const float* __restrict__ Xq, const float* __restrict__ Xk, const float* __restrict__ Xv,
    const float* __restrict__ bq, const float* __restrict__ bk, const float* __restrict__ bv)
{
    const float *X, *bias;
    const int z = blockIdx.z;
    if (z == 0)      { X = Xq; bias = bq; }
    else if (z == 1) { X = Xk; bias = bk; }
    else             { X = Xv; bias = bv; }

    extern __shared__ __align__(16) char sm[];
    float* Xs = (float*)(sm + SM_X);
    const uint32_t smb = smem_u32(sm);
    const int tid = threadIdx.x;
    const int w = tid >> 5, lane = tid & 31;
    const int g = lane >> 2, tg = lane & 3;
    const int row0 = blockIdx.x * 64;

    // stage W fp16 [128 x 64] -> smem rows of 144B (coalesced cp.async)
    const __half* Wg = g_Wh + (size_t)z * DM_ * DD_;
    #pragma unroll
    for (int t = 0; t < 8; t++) {
        int idx = tid + t * 128;
        int r = idx >> 3, c = idx & 7;
        cpasync16(smb + SM_W + r * TROW_B + c * 16, Wg + r * DD_ + c * 8);
    }
    // stage X fp32 [64 x 128] -> rows of 528B
    #pragma unroll
    for (int t = 0; t < 16; t++) {
        int idx = tid + t * 128;
        int r = idx >> 5, c16 = idx & 31;
        cpasync16(smb + SM_X + r * 528 + c16 * 16,
                  X + (size_t)(row0 + r) * DM_ + c16 * 4);
    }
    CP_COMMIT; CP_WAIT0;
    __syncthreads();

    // A fragments: rows r1/r1+8, k-blocks of 16 over DM=128
    const int r1 = w * 16 + g;
    uint32_t aa[8][4];
    #pragma unroll
    for (int s = 0; s < 8; s++) {
        int cb = 16 * s + 2 * tg;
        float2 x0 = *(float2*)(Xs + r1 * 132 + cb);
        float2 x1 = *(float2*)(Xs + (r1 + 8) * 132 + cb);
        float2 x2 = *(float2*)(Xs + r1 * 132 + cb + 8);
        float2 x3 = *(float2*)(Xs + (r1 + 8) * 132 + cb + 8);
        aa[s][0] = f16x2(x0.y, x0.x);
        aa[s][1] = f16x2(x1.y, x1.x);
        aa[s][2] = f16x2(x2.y, x2.x);
        aa[s][3] = f16x2(x3.y, x3.x);
    }

    float c[8][4];
    #pragma unroll
    for (int j = 0; j < 8; j++) { c[j][0]=0.f; c[j][1]=0.f; c[j][2]=0.f; c[j][3]=0.f; }

    const uint32_t wl = smb + SM_W +
        (uint32_t)((((lane >> 3) & 1) * 8 + (lane & 7)) * TROW_B + (lane >> 4) * 16);
    #pragma unroll
    for (int jp = 0; jp < 4; jp++) {
        #pragma unroll
        for (int s = 0; s < 8; s++) {
            uint32_t v0, v1, v2, v3;
            ldsm4t(v0, v1, v2, v3, wl + s * (16 * TROW_B) + jp * 32);
            mma_fp16(c[2*jp],     aa[s], v0, v1);
            mma_fp16(c[2*jp + 1], aa[s], v2, v3);
        }
    }

    // epilogue: bias, (scale), store fp16 dense
    __half* dst = (z == 0) ? g_Qh : (z == 1) ? g_Kh : g_Vh;
    const float osc = (z == 0) ? QSCALE_ : 1.0f;
    const size_t rg1 = (size_t)(row0 + r1), rg2 = rg1 + 8;
    #pragma unroll
    for (int j = 0; j < 8; j++) {
        int n0 = j * 8 + 2 * tg;
        float b0 = bias[n0], b1 = bias[n0 + 1];
        *(uint32_t*)((char*)dst + (rg1 * DD_ + n0) * 2) =
            f16x2((c[j][1] + b1) * osc, (c[j][0] + b0) * osc);
        *(uint32_t*)((char*)dst + (rg2 * DD_ + n0) * 2) =
            f16x2((c[j][3] + b1) * osc, (c[j][2] + b0) * osc);
    }
}

// ---------------------------------------------------------------------------
// Flash attention, all-fp16 mma, split-K(4). CTA = 64 q-rows x 16 key-chunks.
// K fragments via non-trans ldmatrix, V via trans ldmatrix. No max-tracking.
// ---------------------------------------------------------------------------
__global__ __launch_bounds__(128, 4) void attn_mma(void)
{
    extern __shared__ __align__(16) char sm[];
    const uint32_t smb = smem_u32(sm);
    const int tid  = threadIdx.x;
    const int w    = tid >> 5, lane = tid & 31;
    const int g    = lane >> 2, tg = lane & 3;
    const int b    = blockIdx.y;
    const int q0   = blockIdx.x * 64;
    const int sp   = blockIdx.z;
    const int ch0  = sp * NCHS_;

    // ---- Q fragments (fp16, registers) ----
    uint32_t qf[4][4];
    {
        const char* qg = (const char*)g_Qh + ((size_t)b * S_ + q0 + w * 16 + g) * DD_ * 2;
        #pragma unroll
        for (int s = 0; s < 4; s++) {
            int cb = (16 * s + 2 * tg) * 2;
            qf[s][0] = *(const uint32_t*)(qg + cb);
            qf[s][1] = *(const uint32_t*)(qg + 8 * DD_ * 2 + cb);
            qf[s][2] = *(const uint32_t*)(qg + cb + 16);
            qf[s][3] = *(const uint32_t*)(qg + 8 * DD_ * 2 + cb + 16);
        }
    }

    const __half* KhB = g_Kh + (size_t)b * S_ * DD_;
    const __half* VhB = g_Vh + (size_t)b * S_ * DD_;

    // ldmatrix lane offsets
    const uint32_t kl =   // non-trans: 8 key-rows x 4 d-groups
        (uint32_t)((lane & 7) * TROW_B + (lane >> 3) * 16);
    const uint32_t vl =   // trans: 16 key-rows x 2 d-octets
        (uint32_t)((((lane >> 3) & 1) * 8 + (lane & 7)) * TROW_B + (lane >> 4) * 16);

    float o[8][4];
    #pragma unroll
    for (int j = 0; j < 8; j++) { o[j][0]=0.f; o[j][1]=0.f; o[j][2]=0.f; o[j][3]=0.f; }
    float lg = 0.f, lg8 = 0.f;

    auto load_chunk = [&](int ci, int buf) {
        const __half* kc = KhB + (size_t)ci * (64 * DD_);
        const __half* vc = VhB + (size_t)ci * (64 * DD_);
        const uint32_t kd = smb + (buf ? SM_K1 : SM_K0);
        const uint32_t vd = smb + (buf ? SM_V1 : SM_V0);
        #pragma unroll
        for (int t = 0; t < 4; t++) {
            int idx = tid + t * 128;
            int r = idx >> 3, c16 = idx & 7;
            cpasync16(kd + r * TROW_B + c16 * 16, kc + r * DD_ + c16 * 8);
            cpasync16(vd + r * TROW_B + c16 * 16, vc + r * DD_ + c16 * 8);
        }
    };

    load_chunk(ch0, 0); CP_COMMIT;
    CP_WAIT0; __syncthreads();

    #pragma unroll 1
    for (int i = 0; i < NCHS_; i++) {
        const int buf = i & 1;
        if (i + 1 < NCHS_) { load_chunk(ch0 + i + 1, buf ^ 1); CP_COMMIT; }

        // ---- S = Q K^T (fp16) ----
        float c[8][4];
        #pragma unroll
        for (int j = 0; j < 8; j++) { c[j][0]=0.f; c[j][1]=0.f; c[j][2]=0.f; c[j][3]=0.f; }

        const uint32_t kb0 = smb + (buf ? SM_K1 : SM_K0) + kl;
        #pragma unroll
        for (int j = 0; j < 8; j++) {
            uint32_t a = kb0 + j * (8 * TROW_B);
            uint32_t r0, r1, r2, r3, r4, r5, r6, r7;
            ldsm4(r0, r1, r2, r3, a);        // d 0..31
            ldsm4(r4, r5, r6, r7, a + 64);   // d 32..63
            mma_fp16(c[j], qf[0], r0, r1);
            mma_fp16(c[j], qf[1], r2, r3);
            mma_fp16(c[j], qf[2], r4, r5);
            mma_fp16(c[j], qf[3], r6, r7);
        }

        // ---- P = exp2(S), partial row sums ----
        #pragma unroll
        for (int j = 0; j < 8; j++) {
            c[j][0] = ex2f(c[j][0]); c[j][1] = ex2f(c[j][1]);
            c[j][2] = ex2f(c[j][2]); c[j][3] = ex2f(c[j][3]);
            lg  += c[j][0] + c[j][1];
            lg8 += c[j][2] + c[j][3];
        }

        // ---- O += P V ----
        const uint32_t vb0 = smb + (buf ? SM_V1 : SM_V0) + vl;
        #pragma unroll
        for (int s = 0; s < 4; s++) {
            uint32_t pa[4];
            pa[0] = f16x2(c[2*s  ][1], c[2*s  ][0]);
            pa[1] = f16x2(c[2*s  ][3], c[2*s  ][2]);
            pa[2] = f16x2(c[2*s+1][1], c[2*s+1][0]);
            pa[3] = f16x2(c[2*s+1][3], c[2*s+1][2]);
            #pragma unroll
            for (int jp = 0; jp < 4; jp++) {
                uint32_t v0, v1, v2, v3;
                ldsm4t(v0, v1, v2, v3, vb0 + s * (16 * TROW_B) + jp * 32);
                mma_fp16(o[2*jp],     pa, v0, v1);
                mma_fp16(o[2*jp + 1], pa, v2, v3);
            }
        }

        CP_WAIT0;
        __syncthreads();
    }

    // ---- epilogue: partial l + unnormalized partial O ----
    lg  += __shfl_xor_sync(0xffffffffu, lg , 1);
    lg  += __shfl_xor_sync(0xffffffffu, lg , 2);
    lg8 += __shfl_xor_sync(0xffffffffu, lg8, 1);
    lg8 += __shfl_xor_sync(0xffffffffu, lg8, 2);

    const size_t rowg = (size_t)b * S_ + q0 + w * 16 + g;
    float* op = g_Op + ((size_t)sp * NROW_ + rowg) * DD_;
    #pragma unroll
    for (int j = 0; j < 8; j++) {
        *(float2*)(op + j * 8 + tg * 2)           = make_float2(o[j][0], o[j][1]);
        *(float2*)(op + 8 * DD_ + j * 8 + tg * 2) = make_float2(o[j][2], o[j][3]);
    }
    if (tg == 0) {
        g_l[(size_t)sp * NROW_ + rowg]     = lg;
        g_l[(size_t)sp * NROW_ + rowg + 8] = lg8;
    }
}

// ---------------------------------------------------------------------------
// Split-K reduce: out[row] = sum_s Op[s][row] / sum_s l[s][row]
// ---------------------------------------------------------------------------
__global__ __launch_bounds__(256) void reduce_k(float* __restrict__ Out)
{
    const int idx = blockIdx.x * 256 + threadIdx.x;
    const int rid = idx >> 4;
    const int dg  = idx & 15;
    float4 a = make_float4(0.f, 0.f, 0.f, 0.f);
    float ls = 0.f;
    #pragma unroll
    for (int s = 0; s < SPLIT_; s++) {
        float4 v = *(const float4*)(g_Op + ((size_t)s * NROW_ + rid) * DD_ + dg * 4);
        a.x += v.x; a.y += v.y; a.z += v.z; a.w += v.w;
        ls += g_l[(size_t)s * NROW_ + rid];
    }
    const float inv = 1.0f / ls;
    *(float4*)(Out + (size_t)rid * DD_ + dg * 4) =
        make_float4(a.x * inv, a.y * inv, a.z * inv, a.w * inv);
}

// ---------------------------------------------------------------------------
// kernel_launch — graph-capturable, allocation-free
// Inputs (metadata order): q_in, k_in, v_in, Wq, bq, Wk, bk, Wv, bv
// ---------------------------------------------------------------------------
extern "C" void kernel_launch(void* const* d_in, const int* in_sizes, int n_in,
                              void* d_out, int out_size)
{
    const float* q_in = (const float*)d_in[0];
    const float* k_in = (const float*)d_in[1];
    const float* v_in = (const float*)d_in[2];
    const float* Wq   = (const float*)d_in[3];
    const float* bq   = (const float*)d_in[4];
    const float* Wk   = (const float*)d_in[5];
    const float* bk   = (const float*)d_in[6];
    const float* Wv   = (const float*)d_in[7];
    const float* bv   = (const float*)d_in[8];
    float* out = (float*)d_out;

    cudaFuncSetAttribute(proj_tc, cudaFuncAttributeMaxDynamicSharedMemorySize,
                         PROJ_SMEM_);
    cudaFuncSetAttribute(attn_mma, cudaFuncAttributeMaxDynamicSharedMemorySize,
                         SMEM_ATTN_);

    w_prep<<<3, 256>>>(Wq, Wk, Wv);

    proj_tc<<<dim3(NROW_ / 64, 1, 3), 128, PROJ_SMEM_>>>(
        q_in, k_in, v_in, bq, bk, bv);

    attn_mma<<<dim3(S_ / 64, B_, SPLIT_), 128, SMEM_ATTN_>>>();

    reduce_k<<<(NROW_ * 16) / 256, 256>>>(out);
}